// round 16
// baseline (speedup 1.0000x reference)
#include <cuda_runtime.h>
#include <math.h>

#define BN 32
#define TN 4096
#define UN 256
#define NJ 1024
#define CL 8

// ---------------- static device scratch (no runtime allocation) -------------
// padded by one step row so the t+1 prefetch at t = TN-1 stays in bounds
__device__ float g_Zx[(size_t)(TN + 1) * BN * NJ];   // [t*32+b][j] input projection
__device__ float g_Wp[512 * NJ];                     // packed W: rows 0..255 s-part, 256..511 x-part; col j=g*256+u

// ---------------- helpers ----------------------------------------------------
__device__ __forceinline__ unsigned smem_u32(const void* p) {
    unsigned a;
    asm("{ .reg .u64 t; cvta.to.shared.u64 t, %1; cvt.u32.u64 %0, t; }"
        : "=r"(a) : "l"(p));
    return a;
}
__device__ __forceinline__ unsigned long long pk2(float v) {
    unsigned long long r; unsigned u = __float_as_uint(v);
    asm("mov.b64 %0, {%1, %1};" : "=l"(r) : "r"(u));
    return r;
}
__device__ __forceinline__ unsigned long long pack2(float lo, float hi) {
    unsigned long long r;
    asm("mov.b64 %0, {%1, %2};" : "=l"(r)
        : "r"(__float_as_uint(lo)), "r"(__float_as_uint(hi)));
    return r;
}
__device__ __forceinline__ unsigned long long fma2(unsigned long long a,
                                                   unsigned long long b,
                                                   unsigned long long c) {
    unsigned long long d;
    asm("fma.rn.f32x2 %0, %1, %2, %3;" : "=l"(d) : "l"(a), "l"(b), "l"(c));
    return d;
}
__device__ __forceinline__ float2 upk2(unsigned long long v) {
    unsigned lo, hi;
    asm("mov.b64 {%0, %1}, %2;" : "=r"(lo), "=r"(hi) : "l"(v));
    return make_float2(__uint_as_float(lo), __uint_as_float(hi));
}
__device__ __forceinline__ unsigned mapa_u32(unsigned local, unsigned rank) {
    unsigned r;
    asm("mapa.shared::cluster.u32 %0, %1, %2;" : "=r"(r) : "r"(local), "r"(rank));
    return r;
}
__device__ __forceinline__ void mbar_init(unsigned addr, unsigned cnt) {
    asm volatile("mbarrier.init.shared.b64 [%0], %1;" :: "r"(addr), "r"(cnt) : "memory");
}
__device__ __forceinline__ void mbar_expect_tx(unsigned addr, unsigned bytes) {
    asm volatile("mbarrier.arrive.expect_tx.shared.b64 _, [%0], %1;"
                 :: "r"(addr), "r"(bytes) : "memory");
}
// TMA-style wait: CTA-scope acquire, tight poll, no suspend hint.
__device__ __forceinline__ void mbar_wait(unsigned addr, unsigned parity) {
    asm volatile(
        "{\n\t"
        ".reg .pred P;\n\t"
        "WL_%=:\n\t"
        "mbarrier.try_wait.parity.acquire.cta.shared::cta.b64 P, [%0], %1;\n\t"
        "@!P bra WL_%=;\n\t"
        "}"
        :: "r"(addr), "r"(parity) : "memory");
}
// scalar async store to a cluster CTA's SMEM, tx-accounted at remote mbarrier
__device__ __forceinline__ void st_async_f32(unsigned addr, float v, unsigned rbar) {
    asm volatile(
        "st.async.shared::cluster.mbarrier::complete_tx::bytes.f32 [%0], %1, [%2];"
        :: "r"(addr), "f"(v), "r"(rbar) : "memory");
}
// unified gate nonlinearity: A + B / (1 + exp(s*z))
__device__ __forceinline__ float gatefn(float a, float A, float B) {
    float e = __expf(a);
    float r = __fdividef(B, 1.0f + e);
    return A + r;
}
__device__ __forceinline__ float tanh_fast(float z) {
    float e = __expf(2.0f * z);
    return 1.0f - __fdividef(2.0f, 1.0f + e);
}

// ---------------- alignment rotator (so ncu -s 5 lands on k_rec) ------------
__global__ void k_nop() {}

// ---------------- kernel 0: pack weights ------------------------------------
__global__ __launch_bounds__(256) void k_init(const float* __restrict__ Wf,
                                              const float* __restrict__ Wi,
                                              const float* __restrict__ Wc,
                                              const float* __restrict__ Wo) {
    int idx = blockIdx.x * blockDim.x + threadIdx.x;
    if (idx < 512 * 1024) {
        int k = idx >> 10, j = idx & 1023;
        int g = j >> 8,    u = j & 255;
        const float* W = (g == 0) ? Wf : (g == 1) ? Wi : (g == 2) ? Wc : Wo;
        g_Wp[idx] = W[k * 256 + u];
    }
}

// ---------------- kernel 1: input projection GEMM ---------------------------
__global__ __launch_bounds__(256) void k_gemm(const float* __restrict__ x) {
    __shared__ __align__(16) float As[16][64];
    __shared__ __align__(16) float Bs[16][64];

    const int tid = threadIdx.x;
    const int n0  = blockIdx.x * 64;
    const int m0  = blockIdx.y * 64;
    const int tm  = tid >> 4, tn = tid & 15;
    const int ar  = tid >> 2, akq = tid & 3;
    const int bkr = tid >> 4, bnq = tid & 15;

    const int m_glob = m0 + ar;
    const int bb = m_glob & 31, tt = m_glob >> 5;
    const float* arow = x + ((size_t)bb * TN + tt) * 256;

    unsigned long long a00=0, a01=0, a10=0, a11=0, a20=0, a21=0, a30=0, a31=0;

    float4 av = *(const float4*)(arow + akq * 4);
    float4 bv = *(const float4*)(g_Wp + (size_t)(256 + bkr) * NJ + n0 + bnq * 4);

    for (int k0 = 0; k0 < 256; k0 += 16) {
        __syncthreads();
        As[akq * 4 + 0][ar] = av.x;
        As[akq * 4 + 1][ar] = av.y;
        As[akq * 4 + 2][ar] = av.z;
        As[akq * 4 + 3][ar] = av.w;
        *(float4*)&Bs[bkr][bnq * 4] = bv;
        __syncthreads();

        if (k0 + 16 < 256) {
            av = *(const float4*)(arow + k0 + 16 + akq * 4);
            bv = *(const float4*)(g_Wp + (size_t)(256 + k0 + 16 + bkr) * NJ + n0 + bnq * 4);
        }
        #pragma unroll
        for (int kk = 0; kk < 16; kk++) {
            float4 a = *(const float4*)&As[kk][tm * 4];
            ulonglong2 w = *(const ulonglong2*)&Bs[kk][tn * 4];
            unsigned long long p;
            p = pk2(a.x); a00 = fma2(p, w.x, a00); a01 = fma2(p, w.y, a01);
            p = pk2(a.y); a10 = fma2(p, w.x, a10); a11 = fma2(p, w.y, a11);
            p = pk2(a.z); a20 = fma2(p, w.x, a20); a21 = fma2(p, w.y, a21);
            p = pk2(a.w); a30 = fma2(p, w.x, a30); a31 = fma2(p, w.y, a31);
        }
    }
    float2 lo, hi;
    lo = upk2(a00); hi = upk2(a01);
    *(float4*)(g_Zx + (size_t)(m0 + tm*4 + 0) * NJ + n0 + tn*4) = make_float4(lo.x, lo.y, hi.x, hi.y);
    lo = upk2(a10); hi = upk2(a11);
    *(float4*)(g_Zx + (size_t)(m0 + tm*4 + 1) * NJ + n0 + tn*4) = make_float4(lo.x, lo.y, hi.x, hi.y);
    lo = upk2(a20); hi = upk2(a21);
    *(float4*)(g_Zx + (size_t)(m0 + tm*4 + 2) * NJ + n0 + tn*4) = make_float4(lo.x, lo.y, hi.x, hi.y);
    lo = upk2(a30); hi = upk2(a31);
    *(float4*)(g_Zx + (size_t)(m0 + tm*4 + 3) * NJ + n0 + tn*4) = make_float4(lo.x, lo.y, hi.x, hi.y);
}

// ---------------- kernel 2: persistent recurrence (NO block syncs) -----------
// 16 clusters x 8 CTAs; cluster owns batches {2c,2c+1}; CTA rank r owns
// u-slice [r*32,r*32+32). Column-parallel: warp w owns u-pair {2w,2w+1} (8 gate
// cols) x both batches; lane (kq = lane>>3, cl = lane&7) computes a 64-k
// partial of column 8w+cl with k-pair-packed fma2; 2x shfl.bfly reduce over kq.
// Gates+tanh in-warp (lanes 0-15, batch = lane>>3&1); every lane pushes one
// (u,b)->target ct via st.async (one warp instruction). Per-lane waits on the
// 2 source barriers of the lane's k-quarter. Zero __syncthreads in the loop.
// State: Ssm[parity][b][4x68 padded] (kq rows bank-staggered, conflict-free).
__global__ __launch_bounds__(512, 1) __cluster_dims__(CL, 1, 1)
void k_rec(float* __restrict__ out, const float* __restrict__ h0) {
    __shared__ __align__(16) float Ssm[2][2][272];            // [parity][b][kq*68+off]
    __shared__ __align__(8)  unsigned long long mbars[2][8];  // [set = push#&1][source]

    const int tid  = threadIdx.x;
    const int lane = tid & 31;
    const int wid  = tid >> 5;
    unsigned r;
    asm("mov.u32 %0, %%cluster_ctarank;" : "=r"(r));
    const int team = blockIdx.x >> 3;
    const int b0   = team * 2;
    const int u0   = (int)r * 32;

    const int kq = lane >> 3;                 // k-quarter [64kq, 64kq+64)
    const int cl = lane & 7;                  // column within warp
    const int jj = 8 * wid + cl;              // gate-col index 0..127
    const int uu_l = jj >> 2, gg = jj & 3;    // local u, gate
    const int jcol = gg * 256 + u0 + uu_l;    // global Zx column
    const int b_ln = (lane >> 3) & 1;         // batch role (gate/zx/out lanes)
    const size_t c_off = (size_t)BN * TN * UN;

    if (tid < 16) mbar_init(smem_u32(&mbars[tid >> 3][tid & 7]), 1);

    // initial state for step 0 (padded kq rows)
    if (tid < 256) {
        const int idx = (tid >> 6) * 68 + (tid & 63);
        Ssm[0][0][idx] = h0[(b0 + 0) * 256 + tid];
        Ssm[0][1][idx] = h0[(b0 + 1) * 256 + tid];
    }

    // gate-fn constants (f,i,g: sigmoid; o: tanh)
    const float gA = (gg == 3) ? 1.0f : 0.0f;
    const float gB = (gg == 3) ? -2.0f : 1.0f;
    const float gS = (gg == 3) ? 2.0f : -1.0f;

    // weights -> registers: w[p] = (W[64kq+2p][jcol], W[64kq+2p+1][jcol])
    unsigned long long w[32];
    #pragma unroll
    for (int p = 0; p < 32; p++) {
        const float* row = g_Wp + (size_t)(kq * 64 + 2 * p) * NJ + jcol;
        w[p] = pack2(row[0], row[NJ]);
    }

    // remote addressing
    const unsigned SsmB = smem_u32(&Ssm[0][0][0]);
    unsigned m0v[8];
    #pragma unroll
    for (int rk = 0; rk < 8; rk++) m0v[rk] = mapa_u32(SsmB, (unsigned)rk);
    const unsigned barDelta = smem_u32(&mbars[0][0]) - SsmB + (unsigned)r * 8;

    // push role: lane -> (target rk = lane&7, value vi = lane>>3)
    const int b_push = (lane >> 3) & 1;
    const int u_push = u0 + 2 * wid + (lane >> 4);       // vi>>1 = lane>>4
    const int pidx   = (u_push >> 6) * 68 + (u_push & 63);
    const unsigned pushOff0 = (unsigned)((b_push * 272 + pidx) * 4);          // parity 0
    const unsigned pushOff1 = pushOff0 + 2176;                                // parity 1
    const unsigned myTgt = m0v[lane & 7];

    // wait barriers for this lane's k-quarter (sources 2kq, 2kq+1)
    const unsigned wb0 = smem_u32(&mbars[0][2 * kq]);
    const unsigned wb1 = smem_u32(&mbars[1][2 * kq]);
    // re-arm: barrier index == wid (warps 0..7), by a lane that waits on it
    const bool rearm = (wid < 8) && (lane == ((wid >> 1) * 8 + (wid & 1)));
    const unsigned rb0 = smem_u32(&mbars[0][wid & 7]);
    const unsigned rb1 = smem_u32(&mbars[1][wid & 7]);
    if (rearm) { mbar_expect_tx(rb0, 256); mbar_expect_tx(rb1, 256); }

    // s_old address for gate lanes (u = u0 + 2w + ((lane>>2)&1))
    const int u_gate = u0 + 2 * wid + ((lane >> 2) & 1);
    const int sOldIdx = (u_gate >> 6) * 68 + (u_gate & 63);

    // per-step pointers
    const float* zxp = g_Zx + (size_t)(b0 + b_ln) * NJ + jcol;          // += 32*NJ
    float* outH = out + (size_t)(b0 + b_ln) * TN * UN + u_gate;         // += UN
    const bool storer = ((lane & 3) == 0) && (lane < 16);

    __syncthreads();
    asm volatile("barrier.cluster.arrive.aligned;" ::: "memory");
    asm volatile("barrier.cluster.wait.aligned;" ::: "memory");

    float zx_cur = __ldcg(zxp);

    for (int t = 0; t < TN; t++) {
        const int cur = t & 1;

        float zx_nxt = __ldcg(zxp + 32 * NJ);
        zxp += 32 * NJ;

        // per-lane wait on the 2 sources of this lane's k-quarter (push #t-1)
        if (t > 0) {
            const int e = t - 1;
            const unsigned par = (unsigned)((e >> 1) & 1);
            if (e & 1) {
                mbar_wait(wb1, par); mbar_wait(wb1 + 8, par);
                if (rearm) mbar_expect_tx(rb1, 256);
            } else {
                mbar_wait(wb0, par); mbar_wait(wb0 + 8, par);
                if (rearm) mbar_expect_tx(rb0, 256);
            }
        }

        // 64-k partial of one column, both batches, k-pair-packed
        unsigned long long acc0 = 0, acc1 = 0;
        const ulonglong2* S0 = (const ulonglong2*)&Ssm[cur][0][kq * 68];
        const ulonglong2* S1 = (const ulonglong2*)&Ssm[cur][1][kq * 68];
        #pragma unroll
        for (int i = 0; i < 16; i++) {
            ulonglong2 sa = S0[i];
            acc0 = fma2(sa.x, w[2 * i], acc0);
            acc0 = fma2(sa.y, w[2 * i + 1], acc0);
            ulonglong2 sb = S1[i];
            acc1 = fma2(sb.x, w[2 * i], acc1);
            acc1 = fma2(sb.y, w[2 * i + 1], acc1);
        }
        // horizontal add + bfly reduce over kq (xor 8, xor 16) — warp-local
        float2 p0 = upk2(acc0); float z0 = p0.x + p0.y;
        float2 p1 = upk2(acc1); float z1 = p1.x + p1.y;
        z0 += __shfl_xor_sync(0xFFFFFFFFu, z0, 8);
        z0 += __shfl_xor_sync(0xFFFFFFFFu, z0, 16);
        z1 += __shfl_xor_sync(0xFFFFFFFFu, z1, 8);
        z1 += __shfl_xor_sync(0xFFFFFFFFu, z1, 16);

        // gate lanes (0-15): batch b_ln, column jj; add input projection
        float z = (b_ln ? z1 : z0) + zx_cur;
        zx_cur = zx_nxt;

        float v = gatefn(gS * z, gA, gB);
        const int base = lane & ~3;
        float fv = __shfl_sync(0xFFFFFFFFu, v, base + 0);
        float iv = __shfl_sync(0xFFFFFFFFu, v, base + 1);
        float gv = __shfl_sync(0xFFFFFFFFu, v, base + 2);
        float ov = __shfl_sync(0xFFFFFFFFu, v, base + 3);

        float s_old = Ssm[cur][b_ln][sOldIdx];
        float c  = iv * gv + fv * s_old;
        float ct = tanh_fast(c);

        // push: lane ℓ sends ct of (u_sel=ℓ>>4, b=ℓ>>3&1) to target ℓ&7
        float val = __shfl_sync(0xFFFFFFFFu, ct, ((lane >> 3) & 1) * 8 + (lane >> 4) * 4);
        if (t + 1 < TN) {
            st_async_f32(myTgt + (((t + 1) & 1) ? pushOff1 : pushOff0), val,
                         myTgt + barDelta + (unsigned)((t & 1) * 64));
        }

        if (storer) {
            float h = ov * ct;
            outH[0]     = h;
            outH[c_off] = ct;
        }
        outH += UN;
    }
}

// ---------------- launcher ---------------------------------------------------
extern "C" void kernel_launch(void* const* d_in, const int* in_sizes, int n_in,
                              void* d_out, int out_size) {
    const float* x  = (const float*)d_in[0];
    const float* h0 = (const float*)d_in[1];
    const float* Wf = (const float*)d_in[2];
    const float* Wi = (const float*)d_in[3];
    const float* Wc = (const float*)d_in[4];
    const float* Wo = (const float*)d_in[5];
    float* out = (float*)d_out;

    k_nop<<<1, 1>>>();
    k_init<<<2048, 256>>>(Wf, Wi, Wc, Wo);
    dim3 gg(NJ / 64, (TN * BN) / 64);   // (16, 2048)
    k_gemm<<<gg, 256>>>(x);
    k_rec<<<128, 512>>>(out, h0);
}

// round 17
// speedup vs baseline: 1.4467x; 1.4467x over previous
#include <cuda_runtime.h>
#include <math.h>

#define BN 32
#define TN 4096
#define UN 256
#define NJ 1024
#define CL 8

// ---------------- static device scratch (no runtime allocation) -------------
// padded by one step row so the t+1 prefetch at t = TN-1 stays in bounds
__device__ float g_Zx[(size_t)(TN + 1) * BN * NJ];   // [t*32+b][j] input projection
__device__ float g_Wp[512 * NJ];                     // packed W: rows 0..255 s-part, 256..511 x-part; col j=g*256+u

// ---------------- helpers ----------------------------------------------------
__device__ __forceinline__ unsigned smem_u32(const void* p) {
    unsigned a;
    asm("{ .reg .u64 t; cvta.to.shared.u64 t, %1; cvt.u32.u64 %0, t; }"
        : "=r"(a) : "l"(p));
    return a;
}
__device__ __forceinline__ unsigned long long pk2(float v) {
    unsigned long long r; unsigned u = __float_as_uint(v);
    asm("mov.b64 %0, {%1, %1};" : "=l"(r) : "r"(u));
    return r;
}
__device__ __forceinline__ unsigned long long pack2(float lo, float hi) {
    unsigned long long r;
    asm("mov.b64 %0, {%1, %2};" : "=l"(r)
        : "r"(__float_as_uint(lo)), "r"(__float_as_uint(hi)));
    return r;
}
__device__ __forceinline__ unsigned long long fma2(unsigned long long a,
                                                   unsigned long long b,
                                                   unsigned long long c) {
    unsigned long long d;
    asm("fma.rn.f32x2 %0, %1, %2, %3;" : "=l"(d) : "l"(a), "l"(b), "l"(c));
    return d;
}
__device__ __forceinline__ float2 upk2(unsigned long long v) {
    unsigned lo, hi;
    asm("mov.b64 {%0, %1}, %2;" : "=r"(lo), "=r"(hi) : "l"(v));
    return make_float2(__uint_as_float(lo), __uint_as_float(hi));
}
__device__ __forceinline__ unsigned mapa_u32(unsigned local, unsigned rank) {
    unsigned r;
    asm("mapa.shared::cluster.u32 %0, %1, %2;" : "=r"(r) : "r"(local), "r"(rank));
    return r;
}
__device__ __forceinline__ void mbar_init(unsigned addr, unsigned cnt) {
    asm volatile("mbarrier.init.shared.b64 [%0], %1;" :: "r"(addr), "r"(cnt) : "memory");
}
__device__ __forceinline__ void mbar_expect_tx(unsigned addr, unsigned bytes) {
    asm volatile("mbarrier.arrive.expect_tx.shared.b64 _, [%0], %1;"
                 :: "r"(addr), "r"(bytes) : "memory");
}
// TMA-style wait: CTA-scope acquire, tight poll, no suspend hint.
__device__ __forceinline__ void mbar_wait(unsigned addr, unsigned parity) {
    asm volatile(
        "{\n\t"
        ".reg .pred P;\n\t"
        "WL_%=:\n\t"
        "mbarrier.try_wait.parity.acquire.cta.shared::cta.b64 P, [%0], %1;\n\t"
        "@!P bra WL_%=;\n\t"
        "}"
        :: "r"(addr), "r"(parity) : "memory");
}
// scalar async store to a cluster CTA's SMEM, tx-accounted at remote mbarrier
__device__ __forceinline__ void st_async_f32(unsigned addr, float v, unsigned rbar) {
    asm volatile(
        "st.async.shared::cluster.mbarrier::complete_tx::bytes.f32 [%0], %1, [%2];"
        :: "r"(addr), "f"(v), "r"(rbar) : "memory");
}
// unified gate nonlinearity: A + B / (1 + exp(s*z))
__device__ __forceinline__ float gatefn(float a, float A, float B) {
    float e = __expf(a);
    float r = __fdividef(B, 1.0f + e);
    return A + r;
}
__device__ __forceinline__ float tanh_fast(float z) {
    float e = __expf(2.0f * z);
    return 1.0f - __fdividef(2.0f, 1.0f + e);
}

// ---------------- alignment rotator (so ncu -s 5 lands on k_rec) ------------
__global__ void k_nop() {}

// ---------------- kernel 0: pack weights ------------------------------------
__global__ __launch_bounds__(256) void k_init(const float* __restrict__ Wf,
                                              const float* __restrict__ Wi,
                                              const float* __restrict__ Wc,
                                              const float* __restrict__ Wo) {
    int idx = blockIdx.x * blockDim.x + threadIdx.x;
    if (idx < 512 * 1024) {
        int k = idx >> 10, j = idx & 1023;
        int g = j >> 8,    u = j & 255;
        const float* W = (g == 0) ? Wf : (g == 1) ? Wi : (g == 2) ? Wc : Wo;
        g_Wp[idx] = W[k * 256 + u];
    }
}

// ---------------- kernel 1: input projection GEMM (128x64 tile) -------------
// 8m x 4n per thread: 16 fma2 per 3 LDS.128 per kk (2x the arithmetic
// intensity of the old 64x64 tile), half the CTAs, As padded to kill the
// 2-way store conflict.
__global__ __launch_bounds__(256) void k_gemm(const float* __restrict__ x) {
    __shared__ __align__(16) float As[16][132];   // [k][m], padded (+4)
    __shared__ __align__(16) float Bs[16][64];    // [k][n]

    const int tid = threadIdx.x;
    const int n0  = blockIdx.x * 64;
    const int m0  = blockIdx.y * 128;
    const int tm  = tid >> 4, tn = tid & 15;      // 8 m-rows, 4 n-cols each

    const int ar = tid >> 1;                      // A-load row 0..127
    const int ak = (tid & 1) * 4;                 // A-load k-quads: ak, ak+8
    const int bkr = tid >> 4, bnq = tid & 15;     // B-load role

    const int m_glob = m0 + ar;
    const int bb = m_glob & 31, tt = m_glob >> 5;
    const float* arow = x + ((size_t)bb * TN + tt) * 256;

    unsigned long long acc[8][2];
    #pragma unroll
    for (int i = 0; i < 8; i++) { acc[i][0] = 0ull; acc[i][1] = 0ull; }

    float4 av0 = *(const float4*)(arow + ak);
    float4 av1 = *(const float4*)(arow + ak + 8);
    float4 bv  = *(const float4*)(g_Wp + (size_t)(256 + bkr) * NJ + n0 + bnq * 4);

    for (int k0 = 0; k0 < 256; k0 += 16) {
        __syncthreads();
        As[ak + 0][ar] = av0.x;
        As[ak + 1][ar] = av0.y;
        As[ak + 2][ar] = av0.z;
        As[ak + 3][ar] = av0.w;
        As[ak + 8][ar] = av1.x;
        As[ak + 9][ar] = av1.y;
        As[ak + 10][ar] = av1.z;
        As[ak + 11][ar] = av1.w;
        *(float4*)&Bs[bkr][bnq * 4] = bv;
        __syncthreads();

        if (k0 + 16 < 256) {
            av0 = *(const float4*)(arow + k0 + 16 + ak);
            av1 = *(const float4*)(arow + k0 + 16 + ak + 8);
            bv  = *(const float4*)(g_Wp + (size_t)(256 + k0 + 16 + bkr) * NJ + n0 + bnq * 4);
        }
        #pragma unroll
        for (int kk = 0; kk < 16; kk++) {
            float4 a0 = *(const float4*)&As[kk][tm * 8];
            float4 a1 = *(const float4*)&As[kk][tm * 8 + 4];
            ulonglong2 wv = *(const ulonglong2*)&Bs[kk][tn * 4];
            unsigned long long p;
            p = pk2(a0.x); acc[0][0] = fma2(p, wv.x, acc[0][0]); acc[0][1] = fma2(p, wv.y, acc[0][1]);
            p = pk2(a0.y); acc[1][0] = fma2(p, wv.x, acc[1][0]); acc[1][1] = fma2(p, wv.y, acc[1][1]);
            p = pk2(a0.z); acc[2][0] = fma2(p, wv.x, acc[2][0]); acc[2][1] = fma2(p, wv.y, acc[2][1]);
            p = pk2(a0.w); acc[3][0] = fma2(p, wv.x, acc[3][0]); acc[3][1] = fma2(p, wv.y, acc[3][1]);
            p = pk2(a1.x); acc[4][0] = fma2(p, wv.x, acc[4][0]); acc[4][1] = fma2(p, wv.y, acc[4][1]);
            p = pk2(a1.y); acc[5][0] = fma2(p, wv.x, acc[5][0]); acc[5][1] = fma2(p, wv.y, acc[5][1]);
            p = pk2(a1.z); acc[6][0] = fma2(p, wv.x, acc[6][0]); acc[6][1] = fma2(p, wv.y, acc[6][1]);
            p = pk2(a1.w); acc[7][0] = fma2(p, wv.x, acc[7][0]); acc[7][1] = fma2(p, wv.y, acc[7][1]);
        }
    }
    #pragma unroll
    for (int i = 0; i < 8; i++) {
        float2 lo = upk2(acc[i][0]), hi = upk2(acc[i][1]);
        *(float4*)(g_Zx + (size_t)(m0 + tm * 8 + i) * NJ + n0 + tn * 4)
            = make_float4(lo.x, lo.y, hi.x, hi.y);
    }
}

// ---------------- kernel 2: persistent recurrence (R13 verbatim, best) ------
// 16 clusters x 8 CTAs; cluster owns batches {2c,2c+1}; CTA rank r owns
// u-slice [r*32,r*32+32). 16 warps: warp w owns k-slice [16w,16w+16) and waits
// source w>>1's barrier; even warp of each pair re-arms it. Gates/push/output
// on tid<256 (push = 8 scalar st.async per gate thread).
__global__ __launch_bounds__(512, 1) __cluster_dims__(CL, 1, 1)
void k_rec(float* __restrict__ out, const float* __restrict__ h0) {
    __shared__ __align__(16) float Ssm[2][512];        // [parity][k*2 + b]
    __shared__ __align__(16) float Zsm[2][16][264];    // [parity][warp][b*128 + jj]
    __shared__ __align__(8)  unsigned long long mbars[2][8];  // [set = p&1][source]

    const int tid  = threadIdx.x;
    const int lane = tid & 31;
    const int wid  = tid >> 5;
    unsigned r;
    asm("mov.u32 %0, %%cluster_ctarank;" : "=r"(r));
    const int team = blockIdx.x >> 3;
    const int b0   = team * 2;
    const int u0   = (int)r * 32;

    const int jq = lane, kbeg = wid * 16;        // matmul: warp = 16-wide k-slice
    const int jj = tid & 127, bb = (tid >> 7) & 1;  // reduce/gate role (tid<256)
    const int gg = jj & 3,    uu = jj >> 2;
    const int jcol = gg * 256 + u0 + uu;
    const size_t c_off = (size_t)BN * TN * UN;

    if (tid < 16) mbar_init(smem_u32(&mbars[tid >> 3][tid & 7]), 1);

    // initial state for step 0
    if (tid < 256) {
        Ssm[0][tid * 2 + 0] = h0[(b0 + 0) * 256 + tid];
        Ssm[0][tid * 2 + 1] = h0[(b0 + 1) * 256 + tid];
    }

    // gate-fn constants (f,i,g: sigmoid; o: tanh)
    const float gA = (gg == 3) ? 1.0f : 0.0f;
    const float gB = (gg == 3) ? -2.0f : 1.0f;
    const float gS = (gg == 3) ? 2.0f : -1.0f;

    // weights -> registers: w[k][m] packs cols (jq+64m, jq+64m+32), k in slice
    unsigned long long w[16][2];
    #pragma unroll
    for (int k = 0; k < 16; k++) {
        const float* row = g_Wp + (size_t)(kbeg + k) * NJ;
        #pragma unroll
        for (int m = 0; m < 2; m++) {
            int jA = jq + 64 * m, jB = jA + 32;
            int cA = (jA & 3) * 256 + u0 + (jA >> 2);
            int cB = (jB & 3) * 256 + u0 + (jB >> 2);
            w[k][m] = pack2(__ldg(row + cA), __ldg(row + cB));
        }
    }

    // remote addressing: one mapa base per rank; offsets are rank-invariant
    const unsigned SsmB = smem_u32(&Ssm[0][0]);
    unsigned m0v[8];
    #pragma unroll
    for (int rk = 0; rk < 8; rk++) m0v[rk] = mapa_u32(SsmB, (unsigned)rk);
    const unsigned barDelta = smem_u32(&mbars[0][0]) - SsmB + (unsigned)r * 8;
    const unsigned pushOffB = (unsigned)(((u0 + uu) * 2 + bb) * 4);

    const unsigned mywait0 = smem_u32(&mbars[0][wid >> 1]);
    const unsigned mywait1 = smem_u32(&mbars[1][wid >> 1]);
    const bool rearm = (lane == 0) && ((wid & 1) == 0);

    // pre-arm both barrier sets (before cluster barrier -> precedes any push)
    if (rearm) {
        mbar_expect_tx(mywait0, 256);
        mbar_expect_tx(mywait1, 256);
    }

    // per-step incremented pointers
    const float* zxp = g_Zx + (size_t)(b0 + bb) * NJ + jcol;     // += 32*NJ
    float* outH = out + (size_t)(b0 + bb) * TN * UN + (u0 + uu); // += UN

    __syncthreads();
    asm volatile("barrier.cluster.arrive.aligned;" ::: "memory");
    asm volatile("barrier.cluster.wait.aligned;" ::: "memory");

    float zx_cur = (tid < 256) ? __ldcg(zxp) : 0.0f;

    for (int t = 0; t < TN; t++) {
        const int cur = t & 1;

        float zx_nxt = (tid < 256) ? __ldcg(zxp + 32 * NJ) : 0.0f;
        zxp += 32 * NJ;

        // warp-sliced wait on this warp's source slice (push #t-1); even warp
        // of the pair re-arms (before our push #t, which gates push #t+1)
        if (t > 0) {
            const int e = t - 1;
            const unsigned bar = (e & 1) ? mywait1 : mywait0;
            mbar_wait(bar, (unsigned)((e >> 1) & 1));
            if (rearm) mbar_expect_tx(bar, 256);
        }

        // recurrent matmul: 16 k x 2 u64 x 2 batches, weights in registers
        unsigned long long a00=0, a01=0, a10=0, a11=0;
        const float2* Sp = (const float2*)&Ssm[cur][kbeg * 2];
        #pragma unroll
        for (int k = 0; k < 16; k++) {
            float2 s = Sp[k];
            unsigned long long p0 = pk2(s.x), p1 = pk2(s.y);
            a00 = fma2(p0, w[k][0], a00); a01 = fma2(p0, w[k][1], a01);
            a10 = fma2(p1, w[k][0], a10); a11 = fma2(p1, w[k][1], a11);
        }
        // conflict-free partial stores (lane-consecutive STS.32)
        {
            float* zr = &Zsm[cur][wid][0];
            float2 v;
            v = upk2(a00); zr[      jq]      = v.x; zr[      jq + 32] = v.y;
            v = upk2(a01); zr[      jq + 64] = v.x; zr[      jq + 96] = v.y;
            v = upk2(a10); zr[128 + jq]      = v.x; zr[128 + jq + 32] = v.y;
            v = upk2(a11); zr[128 + jq + 64] = v.x; zr[128 + jq + 96] = v.y;
        }

        __syncthreads();   // the ONLY block sync per step

        if (tid < 256) {
            // reduce 16 k-partials + input projection
            float z = zx_cur;
            #pragma unroll
            for (int g = 0; g < 16; g++) z += Zsm[cur][g][bb * 128 + jj];
            zx_cur = zx_nxt;

            // branch-free nonlinearity, gather 4 gates via shuffle
            float v = gatefn(gS * z, gA, gB);
            const int base = lane & ~3;
            float fv = __shfl_sync(0xFFFFFFFFu, v, base + 0);
            float iv = __shfl_sync(0xFFFFFFFFu, v, base + 1);
            float gv = __shfl_sync(0xFFFFFFFFu, v, base + 2);
            float ov = __shfl_sync(0xFFFFFFFFu, v, base + 3);

            if ((tid & 3) == 0) {
                float s_old = Ssm[cur][(u0 + uu) * 2 + bb];
                float c  = iv * gv + fv * s_old;
                float ct = tanh_fast(c);
                float h  = ov * ct;
                // push ct immediately: 8 async scalar stores, tx-accounted
                if (t + 1 < TN) {
                    const unsigned po = pushOffB + (unsigned)(((t + 1) & 1) * 2048);
                    const unsigned bo = barDelta + (unsigned)((t & 1) * 64);
                    #pragma unroll
                    for (int rk = 0; rk < 8; rk++)
                        st_async_f32(m0v[rk] + po, ct, m0v[rk] + bo);
                }
                outH[0]     = h;
                outH[c_off] = ct;
            }
            outH += UN;
        }
    }
}

// ---------------- launcher ---------------------------------------------------
extern "C" void kernel_launch(void* const* d_in, const int* in_sizes, int n_in,
                              void* d_out, int out_size) {
    const float* x  = (const float*)d_in[0];
    const float* h0 = (const float*)d_in[1];
    const float* Wf = (const float*)d_in[2];
    const float* Wi = (const float*)d_in[3];
    const float* Wc = (const float*)d_in[4];
    const float* Wo = (const float*)d_in[5];
    float* out = (float*)d_out;

    k_nop<<<1, 1>>>();
    k_init<<<2048, 256>>>(Wf, Wi, Wc, Wo);
    dim3 gg(NJ / 64, (TN * BN) / 128);   // (16, 1024)
    k_gemm<<<gg, 256>>>(x);
    k_rec<<<128, 512>>>(out, h0);
}